// round 14
// baseline (speedup 1.0000x reference)
#include <cuda_runtime.h>
#include <cstdint>
#include <math.h>

// ---------------- problem constants ----------------
#define FSR    44100.0
#define NS     131072            // samples per channel
#define NCHAN  32                // 4*8 channels
#define CHUNK  32                // samples per chunk (cascade decomposition)
#define NCH    (NS/CHUNK)        // 4096 chunks per channel
#define NSB    256               // superchunks
#define SBC    (NCH/NSB)         // 16 chunks per superchunk
#define EU     32                // leaf envelope block
#define ENB    (NS/EU)           // 4096 leaf blocks
#define NL0    33                // leaf lines
#define NB1    (ENB/2)           // 2048 composed blocks (64 samples each)
#define NL1    65
#define LR1    68                // padded row (floats)
#define EU2    64                // replay granularity
#define EG     8                 // env2 blocks per load group
#define CSH    512.0f            // positivity shift for u32-max trick

// dynamic smem layout for k_pass2e (floats)
#define TILE_SZ (256*33)         // 8448 : gained-input tile
#define SI_SZ   (8*32*NL0)       // 8448
#define SK_SZ   (4*32*67)        // 8576
#define SS_SZ   (32*NL0)         // 1056
#define SOFF_SZ (NL0*32)         // 1056
#define DYN_FLOATS (TILE_SZ + SI_SZ + SK_SZ + SS_SZ + SOFF_SZ)
#define DYN_BYTES  (DYN_FLOATS * 4)

// ---------------- device scratch (static, no allocs) ----------------
__device__ float g_bufB[NCHAN * NS];        // 16 MB : y (post-EQ) [t][c]
__device__ float g_intB[NB1 * NCHAN * LR1]; // 17.8 MB : 65-line maps [p][chan][68]
__device__ float g_hb  [NB1 * NCHAN];       // block-boundary h
__device__ float g_s32 [NCHAN][NL0];        // leaf slopes
__device__ float g_s64 [NCHAN][NL1];        // composed slopes
__device__ float g_off32[NL0][NCHAN];       // C*(1-S) per leaf line
__device__ float g_d12   [NCH * NCHAN * 12];
__device__ float g_start12[NCH * NCHAN * 12];
__device__ float g_T     [NSB * NCHAN * 12];
__device__ float g_sbst  [NSB * NCHAN * 12];
__device__ float g_ML[NCHAN][144];             // M^CHUNK (block lower triangular)
__device__ float g_MS[NCHAN][144];             // M^(CHUNK*SBC)

struct ChParams {
    float b0[6], b1[6], b2[6], a1[6], a2[6];
    float gain;
    float thr, qr, k2, kk, inv2k;      // compressor static curve
    float aa, ar, ka, kr, sigma, mk;   // envelope
    float cth, sth;                    // pan
};
__device__ ChParams g_par[NCHAN];

__device__ const float PLO[26] = {-24.f,-20.f,20.f,0.1f,-20.f,80.f,0.1f,-20.f,200.f,0.1f,-20.f,500.f,0.1f,
                                  -20.f,1000.f,0.1f,-20.f,4000.f,0.1f,-60.f,1.f,1.f,10.f,0.1f,0.f,0.f};
__device__ const float PHI[26] = {24.f,20.f,2000.f,6.f,20.f,2000.f,6.f,20.f,4000.f,6.f,20.f,8000.f,6.f,
                                  20.f,12000.f,6.f,20.f,18000.f,6.f,0.f,10.f,100.f,1000.f,24.f,12.f,1.f};

// triangular packing of the 12x12 block-lower-triangular state matrix:
// row r uses columns 0..NCOLr-1 where NCOLr = 2*(r/2)+2; 84 nonzeros total.
__host__ __device__ constexpr int tri_ncol(int r) { return 2 * (r / 2) + 2; }
__host__ __device__ constexpr int tri_off(int r) {
    int o = 0;
    for (int i = 0; i < r; i++) o += 2 * (i / 2) + 2;
    return o;
}

// knee curve (identical inputs -> identical bits wherever used)
__device__ __forceinline__ float knee_gc(float v, float thr, float qr, float k2c,
                                         float kk, float inv2k) {
    float av  = fmaxf(fabsf(v), 1e-8f);
    float xdb = 6.0205999132796239f * __log2f(av);
    float d   = xdb - thr;
    float t1  = d + k2c;
    float mid = qr * t1 * t1 * inv2k;
    float hi  = qr * d;
    return (t1 <= 0.f) ? 0.f : ((t1 >= kk) ? hi : mid);
}

__device__ __forceinline__ double denorm1(const float* mp, int c, int i) {
    return (double)mp[c * 26 + i] * ((double)PHI[i] - (double)PLO[i]) + (double)PLO[i];
}

// ---------------- merged setup: coefficients + matrix powers, one block/channel ----------------
__device__ void warp_matmul(double* dst, const double* src, int l) {
    for (int e = l; e < 144; e += 32) {
        int r = e / 12, c2 = e % 12;
        double acc = 0.0;
#pragma unroll
        for (int k = 0; k < 12; k++) acc += src[r * 12 + k] * src[k * 12 + c2];
        dst[e] = acc;
    }
}

__global__ void k_setup(const float* __restrict__ mp) {   // <<<32, 64>>>
    __shared__ double SA[144], SB[144];
    int ch = blockIdx.x;
    int tid = threadIdx.x;

    if (tid < 6) {
        // biquad stage coefficients for (ch, stage=tid)
        int stage = tid;
        int base = 1 + 3 * stage;
        double g = denorm1(mp, ch, base);
        double f = denorm1(mp, ch, base + 1);
        double q = denorm1(mp, ch, base + 2);
        double A  = pow(10.0, g / 40.0);
        double w0 = 2.0 * M_PI * f / FSR;
        double cw = cos(w0), sw = sin(w0);
        double alpha = sw / (2.0 * q);
        double b0d, b1d, b2d, a0d, a1d, a2d;
        if (stage == 0 || stage == 5) {
            double sgn = (stage == 0) ? 1.0 : -1.0;
            double s2 = 2.0 * sqrt(A) * alpha;
            b0d = A * (A + 1.0 - sgn * (A - 1.0) * cw + s2);
            b1d = sgn * 2.0 * A * (A - 1.0 - sgn * (A + 1.0) * cw);
            b2d = A * (A + 1.0 - sgn * (A - 1.0) * cw - s2);
            a0d = A + 1.0 + sgn * (A - 1.0) * cw + s2;
            a1d = -sgn * 2.0 * (A - 1.0 + sgn * (A + 1.0) * cw);
            a2d = A + 1.0 + sgn * (A - 1.0) * cw - s2;
        } else {
            b0d = 1.0 + alpha * A;
            b1d = -2.0 * cw;
            b2d = 1.0 - alpha * A;
            a0d = 1.0 + alpha / A;
            a1d = -2.0 * cw;
            a2d = 1.0 - alpha / A;
        }
        ChParams& P = g_par[ch];
        P.b0[stage] = (float)(b0d / a0d);
        P.b1[stage] = (float)(b1d / a0d);
        P.b2[stage] = (float)(b2d / a0d);
        P.a1[stage] = (float)(a1d / a0d);
        P.a2[stage] = (float)(a2d / a0d);
    } else if (tid == 6) {
        // per-channel scalar params + slope tables
        ChParams& P = g_par[ch];
        double p0  = denorm1(mp, ch, 0);
        double p19 = denorm1(mp, ch, 19);
        double p20 = denorm1(mp, ch, 20);
        double p21 = denorm1(mp, ch, 21);
        double p22 = denorm1(mp, ch, 22);
        double p23 = denorm1(mp, ch, 23);
        double p24 = denorm1(mp, ch, 24);
        double p25 = denorm1(mp, ch, 25);
        P.gain = (float)pow(10.0, p0 / 20.0);
        P.thr  = (float)p19;
        P.qr   = (float)(1.0 / p20 - 1.0);
        P.kk   = (float)p23;
        P.k2   = (float)(p23 * 0.5);
        P.inv2k= (float)(1.0 / (2.0 * p23));
        float aa = (float)exp(-1.0 / (FSR * p21 * 0.001));
        float ar = (float)exp(-1.0 / (FSR * p22 * 0.001));
        float omaa = 1.0f - aa;   // replicate reference fp32 rounding
        float omar = 1.0f - ar;
        float sg = (aa >= ar) ? 1.0f : -1.0f;
        P.aa = aa; P.ar = ar;
        P.sigma = sg; P.ka = sg * omaa; P.kr = sg * omar;
        P.mk = (float)p24;
        double th = p25 * (M_PI * 0.5);
        P.cth = (float)cos(th);
        P.sth = (float)sin(th);
        double daa = (double)aa, dar = (double)ar;
        double ratio = daa / dar;
        double ar32 = 1.0;
#pragma unroll
        for (int i = 0; i < EU; i++) ar32 *= dar;     // ar^32
        double s = ar32;
#pragma unroll
        for (int i = 0; i < NL0; i++) {               // aa^i * ar^(32-i)
            g_s32[ch][i]   = (float)s;
            g_off32[i][ch] = (float)((double)CSH * (1.0 - s));
            s *= ratio;
        }
        double s2 = ar32 * ar32;                      // ar^64
        for (int i = 0; i < NL1; i++) {               // aa^i * ar^(64-i)
            g_s64[ch][i] = (float)s2;
            s2 *= ratio;
        }
    }
    __syncthreads();     // g_par[ch] coefficients visible to warp 0

    if (tid >= 32) return;
    int l = tid;
    double* cur = SA;
    double* alt = SB;
    const ChParams& P = g_par[ch];
    if (l < 12) {
        double s[12], ns[12];
#pragma unroll
        for (int i = 0; i < 12; i++) s[i] = (i == l) ? 1.0 : 0.0;
        double in = 0.0;
#pragma unroll
        for (int st = 0; st < 6; st++) {
            double y = (double)P.b0[st] * in + s[2 * st];
            ns[2 * st]     = (double)P.b1[st] * in - (double)P.a1[st] * y + s[2 * st + 1];
            ns[2 * st + 1] = (double)P.b2[st] * in - (double)P.a2[st] * y;
            in = y;
        }
#pragma unroll
        for (int i = 0; i < 12; i++) cur[i * 12 + l] = ns[i];
    }
    __syncwarp();
    // squarings: M^(2^q); store M^32 at q=5, M^512 (=CHUNK*SBC) at q=9
    for (int q = 1; q <= 9; q++) {
        warp_matmul(alt, cur, l);
        __syncwarp();
        double* t = cur; cur = alt; alt = t;
        if (q == 5)
            for (int e = l; e < 144; e += 32) g_ML[ch][e] = (float)cur[e];
    }
    for (int e = l; e < 144; e += 32) g_MS[ch][e] = (float)cur[e];
}

// ---------------- pass1: read tracks, transpose+gain in smem, chunk responses ----------------
__global__ void __launch_bounds__(256) k_pass1t(const float* __restrict__ tracks) {
    __shared__ float tile[256][33];
    int tx = threadIdx.x, ty = threadIdx.y;
    int tid = ty * 32 + tx;
    int t0 = blockIdx.x * 256;
#pragma unroll 4
    for (int c = 0; c < NCHAN; c++) {
        float gn = g_par[c].gain;
        tile[tid][c] = tracks[(size_t)c * NS + t0 + tid] * gn;
    }
    __syncthreads();
    int k = blockIdx.x * 8 + ty;
    const ChParams& P = g_par[tx];
    float b0[6], b1[6], b2[6], a1[6], a2[6];
#pragma unroll
    for (int s = 0; s < 6; s++) { b0[s]=P.b0[s]; b1[s]=P.b1[s]; b2[s]=P.b2[s]; a1[s]=P.a1[s]; a2[s]=P.a2[s]; }
    float s1[6] = {0,0,0,0,0,0}, s2[6] = {0,0,0,0,0,0};
#pragma unroll 8
    for (int t = 0; t < CHUNK; t++) {
        float v = tile[ty * CHUNK + t][tx];
#pragma unroll
        for (int s = 0; s < 6; s++) {
            float y = fmaf(b0[s], v, s1[s]);
            s1[s] = fmaf(-a1[s], y, fmaf(b1[s], v, s2[s]));
            s2[s] = fmaf(-a2[s], y, b2[s] * v);
            v = y;
        }
    }
    float* d = g_d12 + ((size_t)k * NCHAN + tx) * 12;
#pragma unroll
    for (int s = 0; s < 6; s++) { d[2*s] = s1[s]; d[2*s+1] = s2[s]; }
}

// ---------------- hierarchical 12-state scan (triangular-packed M, deep prefetch) ----------------
__device__ __forceinline__ void load12(const float* p, float* v) {
    float4 q0 = *(const float4*)(p);
    float4 q1 = *(const float4*)(p + 4);
    float4 q2 = *(const float4*)(p + 8);
    v[0]=q0.x; v[1]=q0.y; v[2]=q0.z; v[3]=q0.w;
    v[4]=q1.x; v[5]=q1.y; v[6]=q1.z; v[7]=q1.w;
    v[8]=q2.x; v[9]=q2.y; v[10]=q2.z; v[11]=q2.w;
}
__device__ __forceinline__ void store12(float* p, const float* v) {
    *(float4*)(p)     = make_float4(v[0], v[1], v[2], v[3]);
    *(float4*)(p + 4) = make_float4(v[4], v[5], v[6], v[7]);
    *(float4*)(p + 8) = make_float4(v[8], v[9], v[10], v[11]);
}
__device__ __forceinline__ void load_tri(const float* Mfull, float* Mt) {
#pragma unroll
    for (int r = 0; r < 12; r++) {
#pragma unroll
        for (int k2 = 0; k2 < 12; k2++)
            if (k2 < tri_ncol(r)) Mt[tri_off(r) + k2] = Mfull[r * 12 + k2];
    }
}
__device__ __forceinline__ void tri_matvec(const float* Mt, const float* S,
                                           const float* d, float* ns) {
#pragma unroll
    for (int r = 0; r < 12; r++) {
        float acc = d[r];
#pragma unroll
        for (int k2 = 0; k2 < 12; k2++)
            if (k2 < tri_ncol(r)) acc = fmaf(Mt[tri_off(r) + k2], S[k2], acc);
        ns[r] = acc;
    }
}

__global__ void __launch_bounds__(128) k_scanA() {
    int idx = blockIdx.x * blockDim.x + threadIdx.x;   // NSB*NCHAN = 8192
    int ch = idx & (NCHAN - 1), sb = idx >> 5;
    float Mt[84];
    load_tri(g_ML[ch], Mt);
    float S[12];
#pragma unroll
    for (int i = 0; i < 12; i++) S[i] = 0.f;
    const float* dbase = g_d12 + ((size_t)(sb * SBC) * NCHAN + ch) * 12;
    float d0[12], d1[12], d2[12], d3[12];
    load12(dbase, d0);
    load12(dbase + (size_t)1 * NCHAN * 12, d1);
    load12(dbase + (size_t)2 * NCHAN * 12, d2);
#pragma unroll 1
    for (int j = 0; j < SBC; j++) {
        if (j + 3 < SBC) load12(dbase + (size_t)(j + 3) * NCHAN * 12, d3);
        float ns[12];
        tri_matvec(Mt, S, d0, ns);
#pragma unroll
        for (int i = 0; i < 12; i++) { S[i] = ns[i]; d0[i] = d1[i]; d1[i] = d2[i]; d2[i] = d3[i]; }
    }
    store12(g_T + ((size_t)sb * NCHAN + ch) * 12, S);
}

__global__ void __launch_bounds__(32, 1) k_scanB() {
    int ch = threadIdx.x;
    float Mt[84];
    load_tri(g_MS[ch], Mt);
    float S[12];
#pragma unroll
    for (int i = 0; i < 12; i++) S[i] = 0.f;
    float T0[12], T1[12], T2[12];
    load12(g_T + (size_t)ch * 12, T0);
    load12(g_T + ((size_t)NCHAN + ch) * 12, T1);
#pragma unroll 1
    for (int sb = 0; sb < NSB; sb++) {
        store12(g_sbst + ((size_t)sb * NCHAN + ch) * 12, S);
        if (sb + 2 < NSB) load12(g_T + ((size_t)(sb + 2) * NCHAN + ch) * 12, T2);
        float ns[12];
        tri_matvec(Mt, S, T0, ns);
#pragma unroll
        for (int i = 0; i < 12; i++) { S[i] = ns[i]; T0[i] = T1[i]; T1[i] = T2[i]; }
    }
}

__global__ void __launch_bounds__(128) k_scanC() {
    int idx = blockIdx.x * blockDim.x + threadIdx.x;
    int ch = idx & (NCHAN - 1), sb = idx >> 5;
    float Mt[84];
    load_tri(g_ML[ch], Mt);
    float S[12];
    load12(g_sbst + ((size_t)sb * NCHAN + ch) * 12, S);
    const float* dbase = g_d12     + ((size_t)(sb * SBC) * NCHAN + ch) * 12;
    float*       obase = g_start12 + ((size_t)(sb * SBC) * NCHAN + ch) * 12;
    float d0[12], d1[12], d2[12], d3[12];
    load12(dbase, d0);
    load12(dbase + (size_t)1 * NCHAN * 12, d1);
    load12(dbase + (size_t)2 * NCHAN * 12, d2);
#pragma unroll 1
    for (int j = 0; j < SBC; j++) {
        store12(obase + (size_t)j * NCHAN * 12, S);
        if (j + 3 < SBC) load12(dbase + (size_t)(j + 3) * NCHAN * 12, d3);
        float ns[12];
        tri_matvec(Mt, S, d0, ns);
#pragma unroll
        for (int i = 0; i < 12; i++) { S[i] = ns[i]; d0[i] = d1[i]; d1[i] = d2[i]; d2[i] = d3[i]; }
    }
}

// ---------------- fused pass2 + leaf DP + pairwise composition (reads tracks) ----------------
__global__ void __launch_bounds__(256) k_pass2e(const float* __restrict__ tracks,
                                                float* __restrict__ outy) {
    extern __shared__ float dyn[];
    float* tile = dyn;                   // [256][33]
    float* sI   = tile + TILE_SZ;        // [8][32][33]
    float* sK   = sI + SI_SZ;            // [4][32][67]
    float* sS32 = sK + SK_SZ;            // [32][33]
    float* sOff = sS32 + SS_SZ;          // [33][32]
    int tx = threadIdx.x, ty = threadIdx.y;
    int tid = ty * 32 + tx;
    for (int i = tid; i < 32 * NL0; i += 256) sS32[i] = g_s32[i / NL0][i % NL0];
    for (int i = tid; i < NL0 * 32; i += 256) sOff[i] = g_off32[i / 32][i % 32];

    int t0 = blockIdx.x * 256;
#pragma unroll 4
    for (int c0 = 0; c0 < NCHAN; c0++) {
        float gn = g_par[c0].gain;
        tile[tid * 33 + c0] = tracks[(size_t)c0 * NS + t0 + tid] * gn;
    }
    __syncthreads();

    int k = blockIdx.x * 8 + ty;
    int c = tx;
    const ChParams& P = g_par[c];
    float b0[6], b1[6], b2[6], a1[6], a2[6];
#pragma unroll
    for (int s = 0; s < 6; s++) { b0[s]=P.b0[s]; b1[s]=P.b1[s]; b2[s]=P.b2[s]; a1[s]=P.a1[s]; a2[s]=P.a2[s]; }
    float aa = P.aa, ar = P.ar, ka = P.ka, kr = P.kr;
    float thr = P.thr, qr = P.qr, k2c = P.k2, kk = P.kk, inv2k = P.inv2k;
    float s1[6], s2[6];
    const float* st = g_start12 + ((size_t)k * NCHAN + c) * 12;
#pragma unroll
    for (int s = 0; s < 6; s++) { s1[s] = st[2*s]; s2[s] = st[2*s+1]; }
    float* op = outy + (size_t)k * CHUNK * NCHAN + c;
    float I[NL0];
#pragma unroll
    for (int t = 0; t < CHUNK; t++) {
        float v = tile[(ty * CHUNK + t) * 33 + tx];
#pragma unroll
        for (int s = 0; s < 6; s++) {
            float y = fmaf(b0[s], v, s1[s]);
            s1[s] = fmaf(-a1[s], y, fmaf(b1[s], v, s2[s]));
            s2[s] = fmaf(-a2[s], y, b2[s] * v);
            v = y;
        }
        op[(size_t)t * NCHAN] = v;
        float gcv = knee_gc(v, thr, qr, k2c, kk, inv2k);
        float kag = ka * gcv, krg = kr * gcv;
        if (t == 0) {
            I[0] = krg; I[1] = kag;
        } else {
#pragma unroll
            for (int i = NL0 - 1; i >= 1; i--) {
                if (i == t + 1)      I[i] = fmaf(aa, I[i - 1], kag);
                else if (i <= t)     I[i] = fmaxf(fmaf(aa, I[i - 1], kag), fmaf(ar, I[i], krg));
            }
            I[0] = fmaf(ar, I[0], krg);
        }
    }
    __syncthreads();
    float* sIrow = sI + ((size_t)ty * 32 + c) * NL0;
#pragma unroll
    for (int i = 0; i < NL0; i++) sIrow[i] = I[i] + sOff[i * 32 + c];
    __syncthreads();

    {
        int q = ty >> 1;
        int l = tx;
        const float* J1 = sI + ((size_t)(q * 2)     * 32 + l) * NL0;
        const float* J2 = sI + ((size_t)(q * 2 + 1) * 32 + l) * NL0;
        const float* Sc = sS32 + (size_t)l * NL0;
        float* Kq = sK + ((size_t)q * 32 + l) * 67;
        if ((ty & 1) == 0) {
            for (int m = 0; m <= 32; m++) {
                float best = -1e30f;
                for (int i = 0; i <= m; i++)
                    best = fmaxf(best, fmaf(Sc[m - i], J1[i], J2[m - i]));
                Kq[m] = best;
            }
        } else {
            for (int m = 33; m <= 64; m++) {
                float best = -1e30f;
                for (int i = m - 32; i <= 32; i++)
                    best = fmaxf(best, fmaf(Sc[m - i], J1[i], J2[m - i]));
                Kq[m] = best;
            }
        }
    }
    __syncthreads();

    float* outp = g_intB + (size_t)(blockIdx.x * 4) * NCHAN * LR1;
    for (int n = tid; n < 4 * 32 * LR1; n += 256) {
        int q  = n / (32 * LR1);
        int r  = n - q * (32 * LR1);
        int c2 = r / LR1, m = r - c2 * LR1;
        outp[n] = (m <= 64) ? sK[((size_t)q * 32 + c2) * 67 + m] : 0.f;
    }
}

// ---------------- envelope serial scan: 2048 steps, two-deep prefetch ----------------
__global__ void __launch_bounds__(128, 1) k_env2() {
    int w = threadIdx.x >> 5, l = threadIdx.x & 31;
    int c = blockIdx.x * 4 + w;
    float S0 = g_s64[c][l];
    float S1 = g_s64[c][32 + l];
    float SB = g_s64[c][64];
    const float* base = g_intB + (size_t)c * LR1;
    const size_t BSTR = (size_t)NCHAN * LR1;
    float* hb = g_hb + c;

    float2 cur[EG], nxt[EG], nx2[EG];
    float  curb[EG], nxtb[EG], nx2b[EG];
#pragma unroll
    for (int j = 0; j < EG; j++) {
        const float* r = base + (size_t)j * BSTR;
        cur[j]  = make_float2(r[l], r[32 + l]);
        curb[j] = r[64];
    }
#pragma unroll
    for (int j = 0; j < EG; j++) {
        const float* r = base + (size_t)(EG + j) * BSTR;
        nxt[j]  = make_float2(r[l], r[32 + l]);
        nxtb[j] = r[64];
    }
    float h = CSH;
    const int NG = NB1 / EG;
    for (int g = 0; g < NG; g++) {
        if (g + 2 < NG) {
            const float* pbase = base + (size_t)(g + 2) * EG * BSTR;
#pragma unroll
            for (int j = 0; j < EG; j++) {
                const float* r = pbase + (size_t)j * BSTR;
                nx2[j]  = make_float2(r[l], r[32 + l]);
                nx2b[j] = r[64];
            }
        }
#pragma unroll
        for (int j = 0; j < EG; j++) {
            if (l == 0) hb[(size_t)(g * EG + j) * NCHAN] = h - CSH;
            float v0 = fmaf(S0, h, cur[j].x);
            float v1 = fmaf(S1, h, cur[j].y);
            float vb = fmaf(SB, h, curb[j]);
            v0 = fmaxf(v0, v1);
            v0 = fmaxf(v0, vb);
            unsigned m = __reduce_max_sync(0xffffffffu, __float_as_uint(v0));
            h = __uint_as_float(m);
        }
#pragma unroll
        for (int j = 0; j < EG; j++) {
            cur[j] = nxt[j]; curb[j] = nxtb[j];
            nxt[j] = nx2[j]; nxtb[j] = nx2b[j];
        }
    }
}

// ---------------- envelope replay (64 samples) fused with gain/pan/mix ----------------
__global__ void __launch_bounds__(32) k_env3mix(float* __restrict__ out) {
    int c = threadIdx.x;
    int b = blockIdx.x;
    const ChParams& P = g_par[c];
    float aa = P.aa, ar = P.ar, ka = P.ka, kr = P.kr;
    float thr = P.thr, qr = P.qr, k2c = P.k2, kk = P.kk, inv2k = P.inv2k;
    float sigma = P.sigma, mk = P.mk, cth = P.cth, sth = P.sth;
    float h = g_hb[b * NCHAN + c];
    const float* yp = g_bufB + (size_t)b * EU2 * NCHAN + c;
    int batch = c >> 3;
    float* o = out + (size_t)batch * 2 * NS + (size_t)b * EU2;
    bool lead = ((c & 7) == 0);
#pragma unroll 8
    for (int t = 0; t < EU2; t++) {
        float y   = yp[(size_t)t * NCHAN];
        float gc  = knee_gc(y, thr, qr, k2c, kk, inv2k);
        float fa  = fmaf(aa, h, ka * gc);
        float fr  = fmaf(ar, h, kr * gc);
        h = fmaxf(fa, fr);
        float gdb = fmaf(sigma, h, mk);
        float gl  = exp2f(gdb * 0.16609640474436813f);
        float v   = y * gl;
        float sl = cth * v, sr = sth * v;
        sl += __shfl_xor_sync(0xffffffffu, sl, 1);
        sr += __shfl_xor_sync(0xffffffffu, sr, 1);
        sl += __shfl_xor_sync(0xffffffffu, sl, 2);
        sr += __shfl_xor_sync(0xffffffffu, sr, 2);
        sl += __shfl_xor_sync(0xffffffffu, sl, 4);
        sr += __shfl_xor_sync(0xffffffffu, sr, 4);
        if (lead) {
            o[t]      = sl;
            o[NS + t] = sr;
        }
    }
}

// ---------------- launch ----------------
extern "C" void kernel_launch(void* const* d_in, const int* in_sizes, int n_in,
                              void* d_out, int out_size) {
    const float* tracks = (const float*)d_in[0];
    const float* mparam = (const float*)d_in[1];
    float* out = (float*)d_out;

    float* bufB;
    cudaGetSymbolAddress((void**)&bufB, g_bufB);

    static bool attr_set = false;
    if (!attr_set) {
        cudaFuncSetAttribute(k_pass2e, cudaFuncAttributeMaxDynamicSharedMemorySize, DYN_BYTES);
        attr_set = true;
    }

    k_setup<<<32, 64>>>(mparam);
    k_pass1t<<<NCH / 8, dim3(32, 8)>>>(tracks);
    k_scanA<<<(NSB * NCHAN) / 128, 128>>>();
    k_scanB<<<1, 32>>>();
    k_scanC<<<(NSB * NCHAN) / 128, 128>>>();
    k_pass2e<<<NCH / 8, dim3(32, 8), DYN_BYTES>>>(tracks, bufB);   // y + 65-line maps
    k_env2<<<8, 128>>>();
    k_env3mix<<<NB1, 32>>>(out);
}

// round 15
// speedup vs baseline: 1.0271x; 1.0271x over previous
#include <cuda_runtime.h>
#include <cstdint>
#include <math.h>

// ---------------- problem constants ----------------
#define FSR    44100.0
#define NS     131072            // samples per channel
#define NCHAN  32                // 4*8 channels
#define CHUNK  32                // samples per chunk (cascade decomposition)
#define NCH    (NS/CHUNK)        // 4096 chunks per channel
#define NSB    256               // superchunks
#define SBC    (NCH/NSB)         // 16 chunks per superchunk
#define EU     32                // leaf envelope block
#define ENB    (NS/EU)           // 4096 leaf blocks
#define NL0    33                // leaf lines
#define NB1    (ENB/2)           // 2048 composed blocks (64 samples each)
#define NL1    65
#define LR1    68                // padded row (floats)
#define EU2    64                // replay granularity
#define EG     8                 // env2 blocks per load group
#define CSH    512.0f            // positivity shift for u32-max trick

// dynamic smem layout for k_pass2e (floats)
#define TILE_SZ (256*33)         // 8448 : gained-input tile
#define SI_SZ   (8*32*NL0)       // 8448
#define SK_SZ   (4*32*67)        // 8576
#define SS_SZ   (32*NL0)         // 1056
#define SOFF_SZ (NL0*32)         // 1056
#define DYN_FLOATS (TILE_SZ + SI_SZ + SK_SZ + SS_SZ + SOFF_SZ)
#define DYN_BYTES  (DYN_FLOATS * 4)

// ---------------- device scratch (static, no allocs) ----------------
__device__ float g_bufB[NCHAN * NS];        // 16 MB : y (post-EQ) [t][c]
__device__ float g_intB[NB1 * NCHAN * LR1]; // 17.8 MB : 65-line maps [p][chan][68]
__device__ float g_hb  [NB1 * NCHAN];       // block-boundary h
__device__ float g_s32 [NCHAN][NL0];        // leaf slopes
__device__ float g_s64 [NCHAN][NL1];        // composed slopes
__device__ float g_off32[NL0][NCHAN];       // C*(1-S) per leaf line
__device__ float g_d12   [NCH * NCHAN * 12];
__device__ float g_start12[NCH * NCHAN * 12];
__device__ float g_T     [NSB * NCHAN * 12];
__device__ float g_sbst  [NSB * NCHAN * 12];
__device__ float g_ML[NCHAN][144];             // M^CHUNK (block lower triangular)
__device__ float g_MS[NCHAN][144];             // M^(CHUNK*SBC)

struct ChParams {
    float b0[6], b1[6], b2[6], a1[6], a2[6];
    float gain;
    float thr, qr, k2, kk, inv2k;      // compressor static curve
    float aa, ar, ka, kr, sigma, mk;   // envelope
    float cth, sth;                    // pan
};
__device__ ChParams g_par[NCHAN];

__device__ const float PLO[26] = {-24.f,-20.f,20.f,0.1f,-20.f,80.f,0.1f,-20.f,200.f,0.1f,-20.f,500.f,0.1f,
                                  -20.f,1000.f,0.1f,-20.f,4000.f,0.1f,-60.f,1.f,1.f,10.f,0.1f,0.f,0.f};
__device__ const float PHI[26] = {24.f,20.f,2000.f,6.f,20.f,2000.f,6.f,20.f,4000.f,6.f,20.f,8000.f,6.f,
                                  20.f,12000.f,6.f,20.f,18000.f,6.f,0.f,10.f,100.f,1000.f,24.f,12.f,1.f};

// triangular packing of the 12x12 block-lower-triangular state matrix:
// row r uses columns 0..NCOLr-1 where NCOLr = 2*(r/2)+2; 84 nonzeros total.
__host__ __device__ constexpr int tri_ncol(int r) { return 2 * (r / 2) + 2; }
__host__ __device__ constexpr int tri_off(int r) {
    int o = 0;
    for (int i = 0; i < r; i++) o += 2 * (i / 2) + 2;
    return o;
}

// knee curve (identical inputs -> identical bits wherever used)
__device__ __forceinline__ float knee_gc(float v, float thr, float qr, float k2c,
                                         float kk, float inv2k) {
    float av  = fmaxf(fabsf(v), 1e-8f);
    float xdb = 6.0205999132796239f * __log2f(av);
    float d   = xdb - thr;
    float t1  = d + k2c;
    float mid = qr * t1 * t1 * inv2k;
    float hi  = qr * d;
    return (t1 <= 0.f) ? 0.f : ((t1 >= kk) ? hi : mid);
}

__device__ __forceinline__ double denorm1(const float* mp, int c, int i) {
    return (double)mp[c * 26 + i] * ((double)PHI[i] - (double)PLO[i]) + (double)PLO[i];
}

// ---------------- merged setup: coefficients + matrix powers, one block/channel ----------------
__device__ void warp_matmul(double* dst, const double* src, int l) {
    for (int e = l; e < 144; e += 32) {
        int r = e / 12, c2 = e % 12;
        double acc = 0.0;
#pragma unroll
        for (int k = 0; k < 12; k++) acc += src[r * 12 + k] * src[k * 12 + c2];
        dst[e] = acc;
    }
}

__global__ void k_setup(const float* __restrict__ mp) {   // <<<32, 64>>>
    __shared__ double SA[144], SB[144];
    int ch = blockIdx.x;
    int tid = threadIdx.x;

    if (tid < 6) {
        int stage = tid;
        int base = 1 + 3 * stage;
        double g = denorm1(mp, ch, base);
        double f = denorm1(mp, ch, base + 1);
        double q = denorm1(mp, ch, base + 2);
        double A  = pow(10.0, g / 40.0);
        double w0 = 2.0 * M_PI * f / FSR;
        double cw = cos(w0), sw = sin(w0);
        double alpha = sw / (2.0 * q);
        double b0d, b1d, b2d, a0d, a1d, a2d;
        if (stage == 0 || stage == 5) {
            double sgn = (stage == 0) ? 1.0 : -1.0;
            double s2 = 2.0 * sqrt(A) * alpha;
            b0d = A * (A + 1.0 - sgn * (A - 1.0) * cw + s2);
            b1d = sgn * 2.0 * A * (A - 1.0 - sgn * (A + 1.0) * cw);
            b2d = A * (A + 1.0 - sgn * (A - 1.0) * cw - s2);
            a0d = A + 1.0 + sgn * (A - 1.0) * cw + s2;
            a1d = -sgn * 2.0 * (A - 1.0 + sgn * (A + 1.0) * cw);
            a2d = A + 1.0 + sgn * (A - 1.0) * cw - s2;
        } else {
            b0d = 1.0 + alpha * A;
            b1d = -2.0 * cw;
            b2d = 1.0 - alpha * A;
            a0d = 1.0 + alpha / A;
            a1d = -2.0 * cw;
            a2d = 1.0 - alpha / A;
        }
        ChParams& P = g_par[ch];
        P.b0[stage] = (float)(b0d / a0d);
        P.b1[stage] = (float)(b1d / a0d);
        P.b2[stage] = (float)(b2d / a0d);
        P.a1[stage] = (float)(a1d / a0d);
        P.a2[stage] = (float)(a2d / a0d);
    } else if (tid == 6) {
        ChParams& P = g_par[ch];
        double p0  = denorm1(mp, ch, 0);
        double p19 = denorm1(mp, ch, 19);
        double p20 = denorm1(mp, ch, 20);
        double p21 = denorm1(mp, ch, 21);
        double p22 = denorm1(mp, ch, 22);
        double p23 = denorm1(mp, ch, 23);
        double p24 = denorm1(mp, ch, 24);
        double p25 = denorm1(mp, ch, 25);
        P.gain = (float)pow(10.0, p0 / 20.0);
        P.thr  = (float)p19;
        P.qr   = (float)(1.0 / p20 - 1.0);
        P.kk   = (float)p23;
        P.k2   = (float)(p23 * 0.5);
        P.inv2k= (float)(1.0 / (2.0 * p23));
        float aa = (float)exp(-1.0 / (FSR * p21 * 0.001));
        float ar = (float)exp(-1.0 / (FSR * p22 * 0.001));
        float omaa = 1.0f - aa;   // replicate reference fp32 rounding
        float omar = 1.0f - ar;
        float sg = (aa >= ar) ? 1.0f : -1.0f;
        P.aa = aa; P.ar = ar;
        P.sigma = sg; P.ka = sg * omaa; P.kr = sg * omar;
        P.mk = (float)p24;
        double th = p25 * (M_PI * 0.5);
        P.cth = (float)cos(th);
        P.sth = (float)sin(th);
        double daa = (double)aa, dar = (double)ar;
        double ratio = daa / dar;
        double ar32 = 1.0;
#pragma unroll
        for (int i = 0; i < EU; i++) ar32 *= dar;     // ar^32
        double s = ar32;
#pragma unroll
        for (int i = 0; i < NL0; i++) {               // aa^i * ar^(32-i)
            g_s32[ch][i]   = (float)s;
            g_off32[i][ch] = (float)((double)CSH * (1.0 - s));
            s *= ratio;
        }
        double s2 = ar32 * ar32;                      // ar^64
        for (int i = 0; i < NL1; i++) {               // aa^i * ar^(64-i)
            g_s64[ch][i] = (float)s2;
            s2 *= ratio;
        }
    }
    __syncthreads();     // g_par[ch] coefficients visible to warp 0

    if (tid >= 32) return;
    int l = tid;
    double* cur = SA;
    double* alt = SB;
    const ChParams& P = g_par[ch];
    if (l < 12) {
        double s[12], ns[12];
#pragma unroll
        for (int i = 0; i < 12; i++) s[i] = (i == l) ? 1.0 : 0.0;
        double in = 0.0;
#pragma unroll
        for (int st = 0; st < 6; st++) {
            double y = (double)P.b0[st] * in + s[2 * st];
            ns[2 * st]     = (double)P.b1[st] * in - (double)P.a1[st] * y + s[2 * st + 1];
            ns[2 * st + 1] = (double)P.b2[st] * in - (double)P.a2[st] * y;
            in = y;
        }
#pragma unroll
        for (int i = 0; i < 12; i++) cur[i * 12 + l] = ns[i];
    }
    __syncwarp();
    // squarings: M^(2^q); store M^32 at q=5, M^512 (=CHUNK*SBC) at q=9
    for (int q = 1; q <= 9; q++) {
        warp_matmul(alt, cur, l);
        __syncwarp();
        double* t = cur; cur = alt; alt = t;
        if (q == 5)
            for (int e = l; e < 144; e += 32) g_ML[ch][e] = (float)cur[e];
    }
    for (int e = l; e < 144; e += 32) g_MS[ch][e] = (float)cur[e];
}

// ---------------- pass1: read tracks, transpose+gain in smem, chunk responses ----------------
__global__ void __launch_bounds__(256) k_pass1t(const float* __restrict__ tracks) {
    __shared__ float tile[256][33];
    int tx = threadIdx.x, ty = threadIdx.y;
    int tid = ty * 32 + tx;
    int t0 = blockIdx.x * 256;
#pragma unroll 4
    for (int c = 0; c < NCHAN; c++) {
        float gn = g_par[c].gain;
        tile[tid][c] = tracks[(size_t)c * NS + t0 + tid] * gn;
    }
    __syncthreads();
    int k = blockIdx.x * 8 + ty;
    const ChParams& P = g_par[tx];
    float b0[6], b1[6], b2[6], a1[6], a2[6];
#pragma unroll
    for (int s = 0; s < 6; s++) { b0[s]=P.b0[s]; b1[s]=P.b1[s]; b2[s]=P.b2[s]; a1[s]=P.a1[s]; a2[s]=P.a2[s]; }
    float s1[6] = {0,0,0,0,0,0}, s2[6] = {0,0,0,0,0,0};
#pragma unroll 8
    for (int t = 0; t < CHUNK; t++) {
        float v = tile[ty * CHUNK + t][tx];
#pragma unroll
        for (int s = 0; s < 6; s++) {
            float y = fmaf(b0[s], v, s1[s]);
            s1[s] = fmaf(-a1[s], y, fmaf(b1[s], v, s2[s]));
            s2[s] = fmaf(-a2[s], y, b2[s] * v);
            v = y;
        }
    }
    float* d = g_d12 + ((size_t)k * NCHAN + tx) * 12;
#pragma unroll
    for (int s = 0; s < 6; s++) { d[2*s] = s1[s]; d[2*s+1] = s2[s]; }
}

// ---------------- hierarchical 12-state scan ----------------
__device__ __forceinline__ void load12(const float* p, float* v) {
    float4 q0 = *(const float4*)(p);
    float4 q1 = *(const float4*)(p + 4);
    float4 q2 = *(const float4*)(p + 8);
    v[0]=q0.x; v[1]=q0.y; v[2]=q0.z; v[3]=q0.w;
    v[4]=q1.x; v[5]=q1.y; v[6]=q1.z; v[7]=q1.w;
    v[8]=q2.x; v[9]=q2.y; v[10]=q2.z; v[11]=q2.w;
}
__device__ __forceinline__ void store12(float* p, const float* v) {
    *(float4*)(p)     = make_float4(v[0], v[1], v[2], v[3]);
    *(float4*)(p + 4) = make_float4(v[4], v[5], v[6], v[7]);
    *(float4*)(p + 8) = make_float4(v[8], v[9], v[10], v[11]);
}
__device__ __forceinline__ void load_tri(const float* Mfull, float* Mt) {
#pragma unroll
    for (int r = 0; r < 12; r++) {
#pragma unroll
        for (int k2 = 0; k2 < 12; k2++)
            if (k2 < tri_ncol(r)) Mt[tri_off(r) + k2] = Mfull[r * 12 + k2];
    }
}
__device__ __forceinline__ void tri_matvec(const float* Mt, const float* S,
                                           const float* d, float* ns) {
#pragma unroll
    for (int r = 0; r < 12; r++) {
        float acc = d[r];
#pragma unroll
        for (int k2 = 0; k2 < 12; k2++)
            if (k2 < tri_ncol(r)) acc = fmaf(Mt[tri_off(r) + k2], S[k2], acc);
        ns[r] = acc;
    }
}

__global__ void __launch_bounds__(128) k_scanA() {
    int idx = blockIdx.x * blockDim.x + threadIdx.x;   // NSB*NCHAN = 8192
    int ch = idx & (NCHAN - 1), sb = idx >> 5;
    float Mt[84];
    load_tri(g_ML[ch], Mt);
    float S[12];
#pragma unroll
    for (int i = 0; i < 12; i++) S[i] = 0.f;
    const float* dbase = g_d12 + ((size_t)(sb * SBC) * NCHAN + ch) * 12;
    float d[12], dn[12];
    load12(dbase, d);
#pragma unroll 1
    for (int j = 0; j < SBC; j++) {
        if (j + 1 < SBC) load12(dbase + (size_t)(j + 1) * NCHAN * 12, dn);
        float ns[12];
        tri_matvec(Mt, S, d, ns);
#pragma unroll
        for (int i = 0; i < 12; i++) { S[i] = ns[i]; d[i] = dn[i]; }
    }
    store12(g_T + ((size_t)sb * NCHAN + ch) * 12, S);
}

// row-parallel serial scan over superchunks: thread (r, ch), S in shared
__global__ void __launch_bounds__(384, 1) k_scanB() {
    __shared__ float Ssh[2][12][32];
    int tid = threadIdx.x;
    int r = tid >> 5, ch = tid & 31;       // warp = matrix row, lane = channel
    int nc = tri_ncol(r);                  // uniform within warp
    float Mrow[12];
#pragma unroll
    for (int k = 0; k < 12; k++)
        Mrow[k] = (k < nc) ? g_MS[ch][r * 12 + k] : 0.f;
    Ssh[0][r][ch] = 0.f;
    float Sown = 0.f;                      // this thread's S[r][ch]
    float T0 = g_T[((size_t)0 * NCHAN + ch) * 12 + r];
    float T1 = g_T[((size_t)1 * NCHAN + ch) * 12 + r];
    __syncthreads();
    int cur = 0;
#pragma unroll 1
    for (int sb = 0; sb < NSB; sb++) {
        g_sbst[((size_t)sb * NCHAN + ch) * 12 + r] = Sown;
        float T2 = (sb + 2 < NSB) ? g_T[((size_t)(sb + 2) * NCHAN + ch) * 12 + r] : 0.f;
        float acc = T0;
#pragma unroll
        for (int k = 0; k < 12; k++)
            if (k < nc) acc = fmaf(Mrow[k], Ssh[cur][k][ch], acc);
        Ssh[cur ^ 1][r][ch] = acc;
        Sown = acc;
        T0 = T1; T1 = T2;
        cur ^= 1;
        __syncthreads();
    }
}

__global__ void __launch_bounds__(128) k_scanC() {
    int idx = blockIdx.x * blockDim.x + threadIdx.x;
    int ch = idx & (NCHAN - 1), sb = idx >> 5;
    float Mt[84];
    load_tri(g_ML[ch], Mt);
    float S[12];
    load12(g_sbst + ((size_t)sb * NCHAN + ch) * 12, S);
    const float* dbase = g_d12     + ((size_t)(sb * SBC) * NCHAN + ch) * 12;
    float*       obase = g_start12 + ((size_t)(sb * SBC) * NCHAN + ch) * 12;
    float d[12], dn[12];
    load12(dbase, d);
#pragma unroll 1
    for (int j = 0; j < SBC; j++) {
        store12(obase + (size_t)j * NCHAN * 12, S);
        if (j + 1 < SBC) load12(dbase + (size_t)(j + 1) * NCHAN * 12, dn);
        float ns[12];
        tri_matvec(Mt, S, d, ns);
#pragma unroll
        for (int i = 0; i < 12; i++) { S[i] = ns[i]; d[i] = dn[i]; }
    }
}

// ---------------- fused pass2 + leaf DP + pairwise composition (reads tracks) ----------------
__global__ void __launch_bounds__(256) k_pass2e(const float* __restrict__ tracks,
                                                float* __restrict__ outy) {
    extern __shared__ float dyn[];
    float* tile = dyn;                   // [256][33]
    float* sI   = tile + TILE_SZ;        // [8][32][33]
    float* sK   = sI + SI_SZ;            // [4][32][67]
    float* sS32 = sK + SK_SZ;            // [32][33]
    float* sOff = sS32 + SS_SZ;          // [33][32]
    int tx = threadIdx.x, ty = threadIdx.y;
    int tid = ty * 32 + tx;
    for (int i = tid; i < 32 * NL0; i += 256) sS32[i] = g_s32[i / NL0][i % NL0];
    for (int i = tid; i < NL0 * 32; i += 256) sOff[i] = g_off32[i / 32][i % 32];

    int t0 = blockIdx.x * 256;
#pragma unroll 4
    for (int c0 = 0; c0 < NCHAN; c0++) {
        float gn = g_par[c0].gain;
        tile[tid * 33 + c0] = tracks[(size_t)c0 * NS + t0 + tid] * gn;
    }
    __syncthreads();

    int k = blockIdx.x * 8 + ty;
    int c = tx;
    const ChParams& P = g_par[c];
    float b0[6], b1[6], b2[6], a1[6], a2[6];
#pragma unroll
    for (int s = 0; s < 6; s++) { b0[s]=P.b0[s]; b1[s]=P.b1[s]; b2[s]=P.b2[s]; a1[s]=P.a1[s]; a2[s]=P.a2[s]; }
    float aa = P.aa, ar = P.ar, ka = P.ka, kr = P.kr;
    float thr = P.thr, qr = P.qr, k2c = P.k2, kk = P.kk, inv2k = P.inv2k;
    float s1[6], s2[6];
    const float* st = g_start12 + ((size_t)k * NCHAN + c) * 12;
#pragma unroll
    for (int s = 0; s < 6; s++) { s1[s] = st[2*s]; s2[s] = st[2*s+1]; }
    float* op = outy + (size_t)k * CHUNK * NCHAN + c;
    float I[NL0];
#pragma unroll
    for (int t = 0; t < CHUNK; t++) {
        float v = tile[(ty * CHUNK + t) * 33 + tx];
#pragma unroll
        for (int s = 0; s < 6; s++) {
            float y = fmaf(b0[s], v, s1[s]);
            s1[s] = fmaf(-a1[s], y, fmaf(b1[s], v, s2[s]));
            s2[s] = fmaf(-a2[s], y, b2[s] * v);
            v = y;
        }
        op[(size_t)t * NCHAN] = v;
        float gcv = knee_gc(v, thr, qr, k2c, kk, inv2k);
        float kag = ka * gcv, krg = kr * gcv;
        if (t == 0) {
            I[0] = krg; I[1] = kag;
        } else {
#pragma unroll
            for (int i = NL0 - 1; i >= 1; i--) {
                if (i == t + 1)      I[i] = fmaf(aa, I[i - 1], kag);
                else if (i <= t)     I[i] = fmaxf(fmaf(aa, I[i - 1], kag), fmaf(ar, I[i], krg));
            }
            I[0] = fmaf(ar, I[0], krg);
        }
    }
    __syncthreads();
    float* sIrow = sI + ((size_t)ty * 32 + c) * NL0;
#pragma unroll
    for (int i = 0; i < NL0; i++) sIrow[i] = I[i] + sOff[i * 32 + c];
    __syncthreads();

    {
        int q = ty >> 1;
        int l = tx;
        const float* J1 = sI + ((size_t)(q * 2)     * 32 + l) * NL0;
        const float* J2 = sI + ((size_t)(q * 2 + 1) * 32 + l) * NL0;
        const float* Sc = sS32 + (size_t)l * NL0;
        float* Kq = sK + ((size_t)q * 32 + l) * 67;
        if ((ty & 1) == 0) {
            for (int m = 0; m <= 32; m++) {
                float best = -1e30f;
                for (int i = 0; i <= m; i++)
                    best = fmaxf(best, fmaf(Sc[m - i], J1[i], J2[m - i]));
                Kq[m] = best;
            }
        } else {
            for (int m = 33; m <= 64; m++) {
                float best = -1e30f;
                for (int i = m - 32; i <= 32; i++)
                    best = fmaxf(best, fmaf(Sc[m - i], J1[i], J2[m - i]));
                Kq[m] = best;
            }
        }
    }
    __syncthreads();

    float* outp = g_intB + (size_t)(blockIdx.x * 4) * NCHAN * LR1;
    for (int n = tid; n < 4 * 32 * LR1; n += 256) {
        int q  = n / (32 * LR1);
        int r  = n - q * (32 * LR1);
        int c2 = r / LR1, m = r - c2 * LR1;
        outp[n] = (m <= 64) ? sK[((size_t)q * 32 + c2) * 67 + m] : 0.f;
    }
}

// ---------------- envelope serial scan: 2048 steps, two-deep prefetch ----------------
__global__ void __launch_bounds__(128, 1) k_env2() {
    int w = threadIdx.x >> 5, l = threadIdx.x & 31;
    int c = blockIdx.x * 4 + w;
    float S0 = g_s64[c][l];
    float S1 = g_s64[c][32 + l];
    float SB = g_s64[c][64];
    const float* base = g_intB + (size_t)c * LR1;
    const size_t BSTR = (size_t)NCHAN * LR1;
    float* hb = g_hb + c;

    float2 cur[EG], nxt[EG], nx2[EG];
    float  curb[EG], nxtb[EG], nx2b[EG];
#pragma unroll
    for (int j = 0; j < EG; j++) {
        const float* r = base + (size_t)j * BSTR;
        cur[j]  = make_float2(r[l], r[32 + l]);
        curb[j] = r[64];
    }
#pragma unroll
    for (int j = 0; j < EG; j++) {
        const float* r = base + (size_t)(EG + j) * BSTR;
        nxt[j]  = make_float2(r[l], r[32 + l]);
        nxtb[j] = r[64];
    }
    float h = CSH;
    const int NG = NB1 / EG;
    for (int g = 0; g < NG; g++) {
        if (g + 2 < NG) {
            const float* pbase = base + (size_t)(g + 2) * EG * BSTR;
#pragma unroll
            for (int j = 0; j < EG; j++) {
                const float* r = pbase + (size_t)j * BSTR;
                nx2[j]  = make_float2(r[l], r[32 + l]);
                nx2b[j] = r[64];
            }
        }
#pragma unroll
        for (int j = 0; j < EG; j++) {
            if (l == 0) hb[(size_t)(g * EG + j) * NCHAN] = h - CSH;
            float v0 = fmaf(S0, h, cur[j].x);
            float v1 = fmaf(S1, h, cur[j].y);
            float vb = fmaf(SB, h, curb[j]);
            v0 = fmaxf(v0, v1);
            v0 = fmaxf(v0, vb);
            unsigned m = __reduce_max_sync(0xffffffffu, __float_as_uint(v0));
            h = __uint_as_float(m);
        }
#pragma unroll
        for (int j = 0; j < EG; j++) {
            cur[j] = nxt[j]; curb[j] = nxtb[j];
            nxt[j] = nx2[j]; nxtb[j] = nx2b[j];
        }
    }
}

// ---------------- envelope replay (64 samples) fused with gain/pan/mix ----------------
__global__ void __launch_bounds__(32) k_env3mix(float* __restrict__ out) {
    int c = threadIdx.x;
    int b = blockIdx.x;
    const ChParams& P = g_par[c];
    float aa = P.aa, ar = P.ar, ka = P.ka, kr = P.kr;
    float thr = P.thr, qr = P.qr, k2c = P.k2, kk = P.kk, inv2k = P.inv2k;
    float sigma = P.sigma, mk = P.mk, cth = P.cth, sth = P.sth;
    float h = g_hb[b * NCHAN + c];
    const float* yp = g_bufB + (size_t)b * EU2 * NCHAN + c;
    int batch = c >> 3;
    float* o = out + (size_t)batch * 2 * NS + (size_t)b * EU2;
    bool lead = ((c & 7) == 0);
#pragma unroll 8
    for (int t = 0; t < EU2; t++) {
        float y   = yp[(size_t)t * NCHAN];
        float gc  = knee_gc(y, thr, qr, k2c, kk, inv2k);
        float fa  = fmaf(aa, h, ka * gc);
        float fr  = fmaf(ar, h, kr * gc);
        h = fmaxf(fa, fr);
        float gdb = fmaf(sigma, h, mk);
        float gl  = exp2f(gdb * 0.16609640474436813f);
        float v   = y * gl;
        float sl = cth * v, sr = sth * v;
        sl += __shfl_xor_sync(0xffffffffu, sl, 1);
        sr += __shfl_xor_sync(0xffffffffu, sr, 1);
        sl += __shfl_xor_sync(0xffffffffu, sl, 2);
        sr += __shfl_xor_sync(0xffffffffu, sr, 2);
        sl += __shfl_xor_sync(0xffffffffu, sl, 4);
        sr += __shfl_xor_sync(0xffffffffu, sr, 4);
        if (lead) {
            o[t]      = sl;
            o[NS + t] = sr;
        }
    }
}

// ---------------- launch ----------------
extern "C" void kernel_launch(void* const* d_in, const int* in_sizes, int n_in,
                              void* d_out, int out_size) {
    const float* tracks = (const float*)d_in[0];
    const float* mparam = (const float*)d_in[1];
    float* out = (float*)d_out;

    float* bufB;
    cudaGetSymbolAddress((void**)&bufB, g_bufB);

    static bool attr_set = false;
    if (!attr_set) {
        cudaFuncSetAttribute(k_pass2e, cudaFuncAttributeMaxDynamicSharedMemorySize, DYN_BYTES);
        attr_set = true;
    }

    k_setup<<<32, 64>>>(mparam);
    k_pass1t<<<NCH / 8, dim3(32, 8)>>>(tracks);
    k_scanA<<<(NSB * NCHAN) / 128, 128>>>();
    k_scanB<<<1, 384>>>();
    k_scanC<<<(NSB * NCHAN) / 128, 128>>>();
    k_pass2e<<<NCH / 8, dim3(32, 8), DYN_BYTES>>>(tracks, bufB);   // y + 65-line maps
    k_env2<<<8, 128>>>();
    k_env3mix<<<NB1, 32>>>(out);
}

// round 17
// speedup vs baseline: 1.1946x; 1.1631x over previous
#include <cuda_runtime.h>
#include <cstdint>
#include <math.h>

// ---------------- problem constants ----------------
#define FSR    44100.0
#define NS     131072            // samples per channel
#define NCHAN  32                // 4*8 channels
#define CHUNK  32                // samples per chunk (cascade decomposition)
#define NCH    (NS/CHUNK)        // 4096 chunks per channel
#define NSB    256               // superchunks
#define SBC    (NCH/NSB)         // 16 chunks per superchunk
#define NGRP   16                // superchunk groups
#define GSB    (NSB/NGRP)        // 16 superchunks per group
#define EU     32                // leaf envelope block
#define ENB    (NS/EU)           // 4096 leaf blocks
#define NL0    33                // leaf lines
#define NB1    (ENB/2)           // 2048 composed blocks (64 samples each)
#define NL1    65
#define LR1    68                // padded row (floats)
#define EU2    64                // replay granularity
#define EG     8                 // env2 blocks per load group
#define CSH    512.0f            // positivity shift for u32-max trick

// dynamic smem layout for k_pass2e (floats)
#define TILE_SZ (256*33)         // 8448 : gained-input tile
#define SI_SZ   (8*32*NL0)       // 8448
#define SK_SZ   (4*32*67)        // 8576
#define SS_SZ   (32*NL0)         // 1056
#define SOFF_SZ (NL0*32)         // 1056
#define DYN_FLOATS (TILE_SZ + SI_SZ + SK_SZ + SS_SZ + SOFF_SZ)
#define DYN_BYTES  (DYN_FLOATS * 4)

// ---------------- device scratch (static, no allocs) ----------------
__device__ float g_bufB[NCHAN * NS];        // 16 MB : y (post-EQ) [t][c]
__device__ float g_intB[NB1 * NCHAN * LR1]; // 17.8 MB : 65-line maps [p][chan][68]
__device__ float g_hb  [NB1 * NCHAN];       // block-boundary h
__device__ float g_s32 [NCHAN][NL0];        // leaf slopes
__device__ float g_s64 [NCHAN][NL1];        // composed slopes
__device__ float g_off32[NL0][NCHAN];       // C*(1-S) per leaf line
__device__ float g_d12   [NCH * NCHAN * 12];
__device__ float g_start12[NCH * NCHAN * 12];
__device__ float g_T     [NSB * NCHAN * 12];
__device__ float g_sbst  [NSB * NCHAN * 12];
__device__ float g_U     [NGRP * NCHAN * 12];  // group zero-init responses
__device__ float g_G     [NGRP * NCHAN * 12];  // group start states
__device__ float g_ML[NCHAN][144];             // M^CHUNK (block lower triangular)
__device__ float g_MS[NCHAN][144];             // M^(CHUNK*SBC) = M^512
__device__ float g_MX[NCHAN][144];             // M^8192

struct ChParams {
    float b0[6], b1[6], b2[6], a1[6], a2[6];
    float gain;
    float thr, qr, k2, kk, inv2k;      // compressor static curve
    float aa, ar, ka, kr, sigma, mk;   // envelope
    float cth, sth;                    // pan
};
__device__ ChParams g_par[NCHAN];

__device__ const float PLO[26] = {-24.f,-20.f,20.f,0.1f,-20.f,80.f,0.1f,-20.f,200.f,0.1f,-20.f,500.f,0.1f,
                                  -20.f,1000.f,0.1f,-20.f,4000.f,0.1f,-60.f,1.f,1.f,10.f,0.1f,0.f,0.f};
__device__ const float PHI[26] = {24.f,20.f,2000.f,6.f,20.f,2000.f,6.f,20.f,4000.f,6.f,20.f,8000.f,6.f,
                                  20.f,12000.f,6.f,20.f,18000.f,6.f,0.f,10.f,100.f,1000.f,24.f,12.f,1.f};

// triangular packing: row r uses cols 0..2*(r/2)+1; 84 nonzeros total.
__host__ __device__ constexpr int tri_ncol(int r) { return 2 * (r / 2) + 2; }
__host__ __device__ constexpr int tri_off(int r) {
    int o = 0;
    for (int i = 0; i < r; i++) o += 2 * (i / 2) + 2;
    return o;
}

// knee curve (identical inputs -> identical bits wherever used)
__device__ __forceinline__ float knee_gc(float v, float thr, float qr, float k2c,
                                         float kk, float inv2k) {
    float av  = fmaxf(fabsf(v), 1e-8f);
    float xdb = 6.0205999132796239f * __log2f(av);
    float d   = xdb - thr;
    float t1  = d + k2c;
    float mid = qr * t1 * t1 * inv2k;
    float hi  = qr * d;
    return (t1 <= 0.f) ? 0.f : ((t1 >= kk) ? hi : mid);
}

__device__ __forceinline__ double denorm1(const float* mp, int c, int i) {
    return (double)mp[c * 26 + i] * ((double)PHI[i] - (double)PLO[i]) + (double)PLO[i];
}

// ---------------- merged setup: coefficients + matrix powers, one block/channel ----------------
__device__ void warp_matmul(double* dst, const double* src, int l) {
    for (int e = l; e < 144; e += 32) {
        int r = e / 12, c2 = e % 12;
        double acc = 0.0;
#pragma unroll
        for (int k = 0; k < 12; k++) acc += src[r * 12 + k] * src[k * 12 + c2];
        dst[e] = acc;
    }
}

__global__ void k_setup(const float* __restrict__ mp) {   // <<<32, 64>>>
    __shared__ double SA[144], SB[144];
    int ch = blockIdx.x;
    int tid = threadIdx.x;

    if (tid < 6) {
        int stage = tid;
        int base = 1 + 3 * stage;
        double g = denorm1(mp, ch, base);
        double f = denorm1(mp, ch, base + 1);
        double q = denorm1(mp, ch, base + 2);
        double A  = pow(10.0, g / 40.0);
        double w0 = 2.0 * M_PI * f / FSR;
        double cw = cos(w0), sw = sin(w0);
        double alpha = sw / (2.0 * q);
        double b0d, b1d, b2d, a0d, a1d, a2d;
        if (stage == 0 || stage == 5) {
            double sgn = (stage == 0) ? 1.0 : -1.0;
            double s2 = 2.0 * sqrt(A) * alpha;
            b0d = A * (A + 1.0 - sgn * (A - 1.0) * cw + s2);
            b1d = sgn * 2.0 * A * (A - 1.0 - sgn * (A + 1.0) * cw);
            b2d = A * (A + 1.0 - sgn * (A - 1.0) * cw - s2);
            a0d = A + 1.0 + sgn * (A - 1.0) * cw + s2;
            a1d = -sgn * 2.0 * (A - 1.0 + sgn * (A + 1.0) * cw);
            a2d = A + 1.0 + sgn * (A - 1.0) * cw - s2;
        } else {
            b0d = 1.0 + alpha * A;
            b1d = -2.0 * cw;
            b2d = 1.0 - alpha * A;
            a0d = 1.0 + alpha / A;
            a1d = -2.0 * cw;
            a2d = 1.0 - alpha / A;
        }
        ChParams& P = g_par[ch];
        P.b0[stage] = (float)(b0d / a0d);
        P.b1[stage] = (float)(b1d / a0d);
        P.b2[stage] = (float)(b2d / a0d);
        P.a1[stage] = (float)(a1d / a0d);
        P.a2[stage] = (float)(a2d / a0d);
    } else if (tid == 6) {
        ChParams& P = g_par[ch];
        double p0  = denorm1(mp, ch, 0);
        double p19 = denorm1(mp, ch, 19);
        double p20 = denorm1(mp, ch, 20);
        double p21 = denorm1(mp, ch, 21);
        double p22 = denorm1(mp, ch, 22);
        double p23 = denorm1(mp, ch, 23);
        double p24 = denorm1(mp, ch, 24);
        double p25 = denorm1(mp, ch, 25);
        P.gain = (float)pow(10.0, p0 / 20.0);
        P.thr  = (float)p19;
        P.qr   = (float)(1.0 / p20 - 1.0);
        P.kk   = (float)p23;
        P.k2   = (float)(p23 * 0.5);
        P.inv2k= (float)(1.0 / (2.0 * p23));
        float aa = (float)exp(-1.0 / (FSR * p21 * 0.001));
        float ar = (float)exp(-1.0 / (FSR * p22 * 0.001));
        float omaa = 1.0f - aa;   // replicate reference fp32 rounding
        float omar = 1.0f - ar;
        float sg = (aa >= ar) ? 1.0f : -1.0f;
        P.aa = aa; P.ar = ar;
        P.sigma = sg; P.ka = sg * omaa; P.kr = sg * omar;
        P.mk = (float)p24;
        double th = p25 * (M_PI * 0.5);
        P.cth = (float)cos(th);
        P.sth = (float)sin(th);
        double daa = (double)aa, dar = (double)ar;
        double ratio = daa / dar;
        double ar32 = 1.0;
#pragma unroll
        for (int i = 0; i < EU; i++) ar32 *= dar;     // ar^32
        double s = ar32;
#pragma unroll
        for (int i = 0; i < NL0; i++) {               // aa^i * ar^(32-i)
            g_s32[ch][i]   = (float)s;
            g_off32[i][ch] = (float)((double)CSH * (1.0 - s));
            s *= ratio;
        }
        double s2 = ar32 * ar32;                      // ar^64
        for (int i = 0; i < NL1; i++) {               // aa^i * ar^(64-i)
            g_s64[ch][i] = (float)s2;
            s2 *= ratio;
        }
    }
    __syncthreads();     // g_par[ch] coefficients visible to warp 0

    if (tid >= 32) return;
    int l = tid;
    double* cur = SA;
    double* alt = SB;
    const ChParams& P = g_par[ch];
    if (l < 12) {
        double s[12], ns[12];
#pragma unroll
        for (int i = 0; i < 12; i++) s[i] = (i == l) ? 1.0 : 0.0;
        double in = 0.0;
#pragma unroll
        for (int st = 0; st < 6; st++) {
            double y = (double)P.b0[st] * in + s[2 * st];
            ns[2 * st]     = (double)P.b1[st] * in - (double)P.a1[st] * y + s[2 * st + 1];
            ns[2 * st + 1] = (double)P.b2[st] * in - (double)P.a2[st] * y;
            in = y;
        }
#pragma unroll
        for (int i = 0; i < 12; i++) cur[i * 12 + l] = ns[i];
    }
    __syncwarp();
    // squarings: M^(2^q); store M^32 (q=5), M^512 (q=9), M^8192 (q=13)
    for (int q = 1; q <= 13; q++) {
        warp_matmul(alt, cur, l);
        __syncwarp();
        double* t = cur; cur = alt; alt = t;
        if (q == 5)
            for (int e = l; e < 144; e += 32) g_ML[ch][e] = (float)cur[e];
        if (q == 9)
            for (int e = l; e < 144; e += 32) g_MS[ch][e] = (float)cur[e];
    }
    for (int e = l; e < 144; e += 32) g_MX[ch][e] = (float)cur[e];
}

// ---------------- pass1: read tracks, transpose+gain in smem, chunk responses ----------------
__global__ void __launch_bounds__(256) k_pass1t(const float* __restrict__ tracks) {
    __shared__ float tile[256][33];
    int tx = threadIdx.x, ty = threadIdx.y;
    int tid = ty * 32 + tx;
    int t0 = blockIdx.x * 256;
#pragma unroll 4
    for (int c = 0; c < NCHAN; c++) {
        float gn = g_par[c].gain;
        tile[tid][c] = tracks[(size_t)c * NS + t0 + tid] * gn;
    }
    __syncthreads();
    int k = blockIdx.x * 8 + ty;
    const ChParams& P = g_par[tx];
    float b0[6], b1[6], b2[6], a1[6], a2[6];
#pragma unroll
    for (int s = 0; s < 6; s++) { b0[s]=P.b0[s]; b1[s]=P.b1[s]; b2[s]=P.b2[s]; a1[s]=P.a1[s]; a2[s]=P.a2[s]; }
    float s1[6] = {0,0,0,0,0,0}, s2[6] = {0,0,0,0,0,0};
#pragma unroll 8
    for (int t = 0; t < CHUNK; t++) {
        float v = tile[ty * CHUNK + t][tx];
#pragma unroll
        for (int s = 0; s < 6; s++) {
            float y = fmaf(b0[s], v, s1[s]);
            s1[s] = fmaf(-a1[s], y, fmaf(b1[s], v, s2[s]));
            s2[s] = fmaf(-a2[s], y, b2[s] * v);
            v = y;
        }
    }
    float* d = g_d12 + ((size_t)k * NCHAN + tx) * 12;
#pragma unroll
    for (int s = 0; s < 6; s++) { d[2*s] = s1[s]; d[2*s+1] = s2[s]; }
}

// ---------------- hierarchical 12-state scan ----------------
__device__ __forceinline__ void load12(const float* p, float* v) {
    float4 q0 = *(const float4*)(p);
    float4 q1 = *(const float4*)(p + 4);
    float4 q2 = *(const float4*)(p + 8);
    v[0]=q0.x; v[1]=q0.y; v[2]=q0.z; v[3]=q0.w;
    v[4]=q1.x; v[5]=q1.y; v[6]=q1.z; v[7]=q1.w;
    v[8]=q2.x; v[9]=q2.y; v[10]=q2.z; v[11]=q2.w;
}
__device__ __forceinline__ void store12(float* p, const float* v) {
    *(float4*)(p)     = make_float4(v[0], v[1], v[2], v[3]);
    *(float4*)(p + 4) = make_float4(v[4], v[5], v[6], v[7]);
    *(float4*)(p + 8) = make_float4(v[8], v[9], v[10], v[11]);
}
__device__ __forceinline__ void load_tri(const float* Mfull, float* Mt) {
#pragma unroll
    for (int r = 0; r < 12; r++) {
#pragma unroll
        for (int k2 = 0; k2 < 12; k2++)
            if (k2 < tri_ncol(r)) Mt[tri_off(r) + k2] = Mfull[r * 12 + k2];
    }
}
__device__ __forceinline__ void tri_matvec(const float* Mt, const float* S,
                                           const float* d, float* ns) {
#pragma unroll
    for (int r = 0; r < 12; r++) {
        float acc = d[r];
#pragma unroll
        for (int k2 = 0; k2 < 12; k2++)
            if (k2 < tri_ncol(r)) acc = fmaf(Mt[tri_off(r) + k2], S[k2], acc);
        ns[r] = acc;
    }
}

__global__ void __launch_bounds__(128) k_scanA() {
    int idx = blockIdx.x * blockDim.x + threadIdx.x;   // NSB*NCHAN = 8192
    int ch = idx & (NCHAN - 1), sb = idx >> 5;
    float Mt[84];
    load_tri(g_ML[ch], Mt);
    float S[12];
#pragma unroll
    for (int i = 0; i < 12; i++) S[i] = 0.f;
    const float* dbase = g_d12 + ((size_t)(sb * SBC) * NCHAN + ch) * 12;
    float d[12], dn[12];
    load12(dbase, d);
#pragma unroll 1
    for (int j = 0; j < SBC; j++) {
        if (j + 1 < SBC) load12(dbase + (size_t)(j + 1) * NCHAN * 12, dn);
        float ns[12];
        tri_matvec(Mt, S, d, ns);
#pragma unroll
        for (int i = 0; i < 12; i++) { S[i] = ns[i]; d[i] = dn[i]; }
    }
    store12(g_T + ((size_t)sb * NCHAN + ch) * 12, S);
}

// B1: per-group zero-init responses (M^512 over 16 superchunks)
__global__ void __launch_bounds__(128) k_scanB1() {
    int idx = blockIdx.x * blockDim.x + threadIdx.x;   // NGRP*NCHAN = 512
    int ch = idx & (NCHAN - 1), g = idx >> 5;
    float Mt[84];
    load_tri(g_MS[ch], Mt);
    float S[12];
#pragma unroll
    for (int i = 0; i < 12; i++) S[i] = 0.f;
    const float* tbase = g_T + ((size_t)(g * GSB) * NCHAN + ch) * 12;
    float d[12], dn[12];
    load12(tbase, d);
#pragma unroll 1
    for (int j = 0; j < GSB; j++) {
        if (j + 1 < GSB) load12(tbase + (size_t)(j + 1) * NCHAN * 12, dn);
        float ns[12];
        tri_matvec(Mt, S, d, ns);
#pragma unroll
        for (int i = 0; i < 12; i++) { S[i] = ns[i]; d[i] = dn[i]; }
    }
    store12(g_U + ((size_t)g * NCHAN + ch) * 12, S);
}

// B2: serial over 16 groups (M^8192)
__global__ void __launch_bounds__(32, 1) k_scanB2() {
    int ch = threadIdx.x;
    float Mt[84];
    load_tri(g_MX[ch], Mt);
    float S[12];
#pragma unroll
    for (int i = 0; i < 12; i++) S[i] = 0.f;
    float d[12], dn[12];
    load12(g_U + (size_t)ch * 12, d);
#pragma unroll 1
    for (int g = 0; g < NGRP; g++) {
        store12(g_G + ((size_t)g * NCHAN + ch) * 12, S);
        if (g + 1 < NGRP) load12(g_U + ((size_t)(g + 1) * NCHAN + ch) * 12, dn);
        float ns[12];
        tri_matvec(Mt, S, d, ns);
#pragma unroll
        for (int i = 0; i < 12; i++) { S[i] = ns[i]; d[i] = dn[i]; }
    }
}

// B3: re-scan within group from its start state, writing superchunk starts
__global__ void __launch_bounds__(128) k_scanB3() {
    int idx = blockIdx.x * blockDim.x + threadIdx.x;   // NGRP*NCHAN = 512
    int ch = idx & (NCHAN - 1), g = idx >> 5;
    float Mt[84];
    load_tri(g_MS[ch], Mt);
    float S[12];
    load12(g_G + ((size_t)g * NCHAN + ch) * 12, S);
    const float* tbase = g_T    + ((size_t)(g * GSB) * NCHAN + ch) * 12;
    float*       obase = g_sbst + ((size_t)(g * GSB) * NCHAN + ch) * 12;
    float d[12], dn[12];
    load12(tbase, d);
#pragma unroll 1
    for (int j = 0; j < GSB; j++) {
        store12(obase + (size_t)j * NCHAN * 12, S);
        if (j + 1 < GSB) load12(tbase + (size_t)(j + 1) * NCHAN * 12, dn);
        float ns[12];
        tri_matvec(Mt, S, d, ns);
#pragma unroll
        for (int i = 0; i < 12; i++) { S[i] = ns[i]; d[i] = dn[i]; }
    }
}

__global__ void __launch_bounds__(128) k_scanC() {
    int idx = blockIdx.x * blockDim.x + threadIdx.x;
    int ch = idx & (NCHAN - 1), sb = idx >> 5;
    float Mt[84];
    load_tri(g_ML[ch], Mt);
    float S[12];
    load12(g_sbst + ((size_t)sb * NCHAN + ch) * 12, S);
    const float* dbase = g_d12     + ((size_t)(sb * SBC) * NCHAN + ch) * 12;
    float*       obase = g_start12 + ((size_t)(sb * SBC) * NCHAN + ch) * 12;
    float d[12], dn[12];
    load12(dbase, d);
#pragma unroll 1
    for (int j = 0; j < SBC; j++) {
        store12(obase + (size_t)j * NCHAN * 12, S);
        if (j + 1 < SBC) load12(dbase + (size_t)(j + 1) * NCHAN * 12, dn);
        float ns[12];
        tri_matvec(Mt, S, d, ns);
#pragma unroll
        for (int i = 0; i < 12; i++) { S[i] = ns[i]; d[i] = dn[i]; }
    }
}

// ---------------- fused pass2 + leaf DP + pairwise composition (reads tracks) ----------------
__global__ void __launch_bounds__(256) k_pass2e(const float* __restrict__ tracks,
                                                float* __restrict__ outy) {
    extern __shared__ float dyn[];
    float* tile = dyn;                   // [256][33]
    float* sI   = tile + TILE_SZ;        // [8][32][33]
    float* sK   = sI + SI_SZ;            // [4][32][67]
    float* sS32 = sK + SK_SZ;            // [32][33]
    float* sOff = sS32 + SS_SZ;          // [33][32]
    int tx = threadIdx.x, ty = threadIdx.y;
    int tid = ty * 32 + tx;
    for (int i = tid; i < 32 * NL0; i += 256) sS32[i] = g_s32[i / NL0][i % NL0];
    for (int i = tid; i < NL0 * 32; i += 256) sOff[i] = g_off32[i / 32][i % 32];

    int t0 = blockIdx.x * 256;
#pragma unroll 4
    for (int c0 = 0; c0 < NCHAN; c0++) {
        float gn = g_par[c0].gain;
        tile[tid * 33 + c0] = tracks[(size_t)c0 * NS + t0 + tid] * gn;
    }
    __syncthreads();

    int k = blockIdx.x * 8 + ty;
    int c = tx;
    const ChParams& P = g_par[c];
    float b0[6], b1[6], b2[6], a1[6], a2[6];
#pragma unroll
    for (int s = 0; s < 6; s++) { b0[s]=P.b0[s]; b1[s]=P.b1[s]; b2[s]=P.b2[s]; a1[s]=P.a1[s]; a2[s]=P.a2[s]; }
    float aa = P.aa, ar = P.ar, ka = P.ka, kr = P.kr;
    float thr = P.thr, qr = P.qr, k2c = P.k2, kk = P.kk, inv2k = P.inv2k;
    float s1[6], s2[6];
    const float* st = g_start12 + ((size_t)k * NCHAN + c) * 12;
#pragma unroll
    for (int s = 0; s < 6; s++) { s1[s] = st[2*s]; s2[s] = st[2*s+1]; }
    float* op = outy + (size_t)k * CHUNK * NCHAN + c;
    float I[NL0];
#pragma unroll
    for (int t = 0; t < CHUNK; t++) {
        float v = tile[(ty * CHUNK + t) * 33 + tx];
#pragma unroll
        for (int s = 0; s < 6; s++) {
            float y = fmaf(b0[s], v, s1[s]);
            s1[s] = fmaf(-a1[s], y, fmaf(b1[s], v, s2[s]));
            s2[s] = fmaf(-a2[s], y, b2[s] * v);
            v = y;
        }
        op[(size_t)t * NCHAN] = v;
        float gcv = knee_gc(v, thr, qr, k2c, kk, inv2k);
        float kag = ka * gcv, krg = kr * gcv;
        if (t == 0) {
            I[0] = krg; I[1] = kag;
        } else {
#pragma unroll
            for (int i = NL0 - 1; i >= 1; i--) {
                if (i == t + 1)      I[i] = fmaf(aa, I[i - 1], kag);
                else if (i <= t)     I[i] = fmaxf(fmaf(aa, I[i - 1], kag), fmaf(ar, I[i], krg));
            }
            I[0] = fmaf(ar, I[0], krg);
        }
    }
    __syncthreads();
    float* sIrow = sI + ((size_t)ty * 32 + c) * NL0;
#pragma unroll
    for (int i = 0; i < NL0; i++) sIrow[i] = I[i] + sOff[i * 32 + c];
    __syncthreads();

    {
        int q = ty >> 1;
        int l = tx;
        const float* J1 = sI + ((size_t)(q * 2)     * 32 + l) * NL0;
        const float* J2 = sI + ((size_t)(q * 2 + 1) * 32 + l) * NL0;
        const float* Sc = sS32 + (size_t)l * NL0;
        float* Kq = sK + ((size_t)q * 32 + l) * 67;
        if ((ty & 1) == 0) {
            for (int m = 0; m <= 32; m++) {
                float best = -1e30f;
                for (int i = 0; i <= m; i++)
                    best = fmaxf(best, fmaf(Sc[m - i], J1[i], J2[m - i]));
                Kq[m] = best;
            }
        } else {
            for (int m = 33; m <= 64; m++) {
                float best = -1e30f;
                for (int i = m - 32; i <= 32; i++)
                    best = fmaxf(best, fmaf(Sc[m - i], J1[i], J2[m - i]));
                Kq[m] = best;
            }
        }
    }
    __syncthreads();

    float* outp = g_intB + (size_t)(blockIdx.x * 4) * NCHAN * LR1;
    for (int n = tid; n < 4 * 32 * LR1; n += 256) {
        int q  = n / (32 * LR1);
        int r  = n - q * (32 * LR1);
        int c2 = r / LR1, m = r - c2 * LR1;
        outp[n] = (m <= 64) ? sK[((size_t)q * 32 + c2) * 67 + m] : 0.f;
    }
}

// ---------------- envelope serial scan: 2048 steps, two-deep prefetch ----------------
__global__ void __launch_bounds__(128, 1) k_env2() {
    int w = threadIdx.x >> 5, l = threadIdx.x & 31;
    int c = blockIdx.x * 4 + w;
    float S0 = g_s64[c][l];
    float S1 = g_s64[c][32 + l];
    float SB = g_s64[c][64];
    const float* base = g_intB + (size_t)c * LR1;
    const size_t BSTR = (size_t)NCHAN * LR1;
    float* hb = g_hb + c;

    float2 cur[EG], nxt[EG], nx2[EG];
    float  curb[EG], nxtb[EG], nx2b[EG];
#pragma unroll
    for (int j = 0; j < EG; j++) {
        const float* r = base + (size_t)j * BSTR;
        cur[j]  = make_float2(r[l], r[32 + l]);
        curb[j] = r[64];
    }
#pragma unroll
    for (int j = 0; j < EG; j++) {
        const float* r = base + (size_t)(EG + j) * BSTR;
        nxt[j]  = make_float2(r[l], r[32 + l]);
        nxtb[j] = r[64];
    }
    float h = CSH;
    const int NG = NB1 / EG;
    for (int g = 0; g < NG; g++) {
        if (g + 2 < NG) {
            const float* pbase = base + (size_t)(g + 2) * EG * BSTR;
#pragma unroll
            for (int j = 0; j < EG; j++) {
                const float* r = pbase + (size_t)j * BSTR;
                nx2[j]  = make_float2(r[l], r[32 + l]);
                nx2b[j] = r[64];
            }
        }
#pragma unroll
        for (int j = 0; j < EG; j++) {
            if (l == 0) hb[(size_t)(g * EG + j) * NCHAN] = h - CSH;
            float v0 = fmaf(S0, h, cur[j].x);
            float v1 = fmaf(S1, h, cur[j].y);
            float vb = fmaf(SB, h, curb[j]);
            v0 = fmaxf(v0, v1);
            v0 = fmaxf(v0, vb);
            unsigned m = __reduce_max_sync(0xffffffffu, __float_as_uint(v0));
            h = __uint_as_float(m);
        }
#pragma unroll
        for (int j = 0; j < EG; j++) {
            cur[j] = nxt[j]; curb[j] = nxtb[j];
            nxt[j] = nx2[j]; nxtb[j] = nx2b[j];
        }
    }
}

// ---------------- envelope replay (64 samples) fused with gain/pan/mix ----------------
__global__ void __launch_bounds__(32) k_env3mix(float* __restrict__ out) {
    int c = threadIdx.x;
    int b = blockIdx.x;
    const ChParams& P = g_par[c];
    float aa = P.aa, ar = P.ar, ka = P.ka, kr = P.kr;
    float thr = P.thr, qr = P.qr, k2c = P.k2, kk = P.kk, inv2k = P.inv2k;
    float sigma = P.sigma, mk = P.mk, cth = P.cth, sth = P.sth;
    float h = g_hb[b * NCHAN + c];
    const float* yp = g_bufB + (size_t)b * EU2 * NCHAN + c;
    int batch = c >> 3;
    float* o = out + (size_t)batch * 2 * NS + (size_t)b * EU2;
    bool lead = ((c & 7) == 0);
#pragma unroll 8
    for (int t = 0; t < EU2; t++) {
        float y   = yp[(size_t)t * NCHAN];
        float gc  = knee_gc(y, thr, qr, k2c, kk, inv2k);
        float fa  = fmaf(aa, h, ka * gc);
        float fr  = fmaf(ar, h, kr * gc);
        h = fmaxf(fa, fr);
        float gdb = fmaf(sigma, h, mk);
        float gl  = exp2f(gdb * 0.16609640474436813f);
        float v   = y * gl;
        float sl = cth * v, sr = sth * v;
        sl += __shfl_xor_sync(0xffffffffu, sl, 1);
        sr += __shfl_xor_sync(0xffffffffu, sr, 1);
        sl += __shfl_xor_sync(0xffffffffu, sl, 2);
        sr += __shfl_xor_sync(0xffffffffu, sr, 2);
        sl += __shfl_xor_sync(0xffffffffu, sl, 4);
        sr += __shfl_xor_sync(0xffffffffu, sr, 4);
        if (lead) {
            o[t]      = sl;
            o[NS + t] = sr;
        }
    }
}

// ---------------- launch ----------------
extern "C" void kernel_launch(void* const* d_in, const int* in_sizes, int n_in,
                              void* d_out, int out_size) {
    const float* tracks = (const float*)d_in[0];
    const float* mparam = (const float*)d_in[1];
    float* out = (float*)d_out;

    float* bufB;
    cudaGetSymbolAddress((void**)&bufB, g_bufB);

    static bool attr_set = false;
    if (!attr_set) {
        cudaFuncSetAttribute(k_pass2e, cudaFuncAttributeMaxDynamicSharedMemorySize, DYN_BYTES);
        attr_set = true;
    }

    k_setup<<<32, 64>>>(mparam);
    k_pass1t<<<NCH / 8, dim3(32, 8)>>>(tracks);
    k_scanA<<<(NSB * NCHAN) / 128, 128>>>();
    k_scanB1<<<(NGRP * NCHAN) / 128, 128>>>();
    k_scanB2<<<1, 32>>>();
    k_scanB3<<<(NGRP * NCHAN) / 128, 128>>>();
    k_scanC<<<(NSB * NCHAN) / 128, 128>>>();
    k_pass2e<<<NCH / 8, dim3(32, 8), DYN_BYTES>>>(tracks, bufB);   // y + 65-line maps
    k_env2<<<8, 128>>>();
    k_env3mix<<<NB1, 32>>>(out);
}